// round 3
// baseline (speedup 1.0000x reference)
#include <cuda_runtime.h>

#define NB 64
#define NT 256
#define MAXG 4096

__device__ float        g_partials[NB];
__device__ unsigned int g_bar;   // monotonic ticket counter (never reset)

__global__ void __launch_bounds__(NT, 2)
ril_fused_kernel(const float* __restrict__ x,
                 const float* __restrict__ weights,
                 const float* __restrict__ min_vals,
                 const float* __restrict__ max_vals,
                 const int* __restrict__ start_pos,
                 const int* __restrict__ offsets,
                 const int* __restrict__ sizes,
                 const int* __restrict__ out_mask,
                 float* __restrict__ out,
                 int B, int D, int G, int Wn, int OUTN, int total)
{
    extern __shared__ float smv[];  // G floats: min_vals

    for (int i = threadIdx.x; i < G; i += NT) smv[i] = __ldg(&min_vals[i]);
    __syncthreads();

    // ---- Phase 1: partial dot-product over this block's elements ----
    const int t  = blockIdx.x * NT + threadIdx.x;
    const int i0 = t * 4;
    const float inv_b = 1.0f / (float)B;
    float acc = 0.0f;

    if (i0 + 3 < D) {
        float4 s4 = make_float4(0.f, 0.f, 0.f, 0.f);
        #pragma unroll 8
        for (int b = 0; b < B; ++b) {
            const float4 xv = __ldg((const float4*)(x + (size_t)b * D + i0));
            s4.x += xv.x; s4.y += xv.y; s4.z += xv.z; s4.w += xv.w;
        }
        float v[4] = { s4.x * inv_b, s4.y * inv_b, s4.z * inv_b, s4.w * inv_b };
        #pragma unroll
        for (int k = 0; k < 4; ++k) {
            float vv = v[k];
            int lo = 0, hi = G;
            #pragma unroll 4
            while (lo < hi) {
                int mid = (lo + hi) >> 1;
                if (smv[mid] <= vv) lo = mid + 1; else hi = mid;
            }
            int g  = lo - 1;
            int gc = min(max(g, 0), G - 1);
            bool in_range = (g >= 0) && (vv >= smv[gc]) && (vv <= __ldg(&max_vals[gc]));
            int pos = (i0 + k) - __ldg(&start_pos[gc]);
            bool valid = in_range && (pos >= 0) && (pos < __ldg(&sizes[gc]));
            int widx = __ldg(&offsets[gc]) + pos;
            widx = min(max(widx, 0), Wn - 1);
            float w = valid ? __ldg(&weights[widx]) : 0.0f;
            acc += vv * w;
        }
    } else {
        for (int i = i0; i < min(i0 + 4, D); ++i) {
            float s = 0.0f;
            for (int b = 0; b < B; ++b) s += x[(size_t)b * D + i];
            float vv = s * inv_b;
            int lo = 0, hi = G;
            while (lo < hi) {
                int mid = (lo + hi) >> 1;
                if (smv[mid] <= vv) lo = mid + 1; else hi = mid;
            }
            int g  = lo - 1;
            int gc = min(max(g, 0), G - 1);
            bool in_range = (g >= 0) && (vv >= smv[gc]) && (vv <= max_vals[gc]);
            int pos = i - start_pos[gc];
            bool valid = in_range && (pos >= 0) && (pos < sizes[gc]);
            int widx = offsets[gc] + pos;
            widx = min(max(widx, 0), Wn - 1);
            float w = valid ? weights[widx] : 0.0f;
            acc += vv * w;
        }
    }

    // Block reduction
    #pragma unroll
    for (int o = 16; o > 0; o >>= 1)
        acc += __shfl_down_sync(0xffffffffu, acc, o);
    __shared__ float red[NT / 32];
    const int lane = threadIdx.x & 31;
    const int wid  = threadIdx.x >> 5;
    if (lane == 0) red[wid] = acc;
    __syncthreads();
    if (threadIdx.x == 0) {
        float p = 0.0f;
        #pragma unroll
        for (int k = 0; k < NT / 32; ++k) p += red[k];
        g_partials[blockIdx.x] = p;
    }

    // ---- Device-wide barrier (ticket, monotonic — survives graph replays) ----
    if (threadIdx.x == 0) {
        __threadfence();
        unsigned int arrival = atomicAdd(&g_bar, 1u) + 1u;
        unsigned int target  = ((arrival - 1u) / gridDim.x + 1u) * gridDim.x;
        unsigned int c;
        do {
            asm volatile("ld.acquire.gpu.u32 %0, [%1];" : "=r"(c) : "l"(&g_bar));
        } while (c < target);
    }
    __syncthreads();

    // ---- Phase 2: every block sums all partials (deterministic order) ----
    __shared__ float sp[NB];
    __shared__ float s_val;
    if (threadIdx.x < NB)
        sp[threadIdx.x] = *(volatile float*)&g_partials[threadIdx.x];
    __syncthreads();
    if (threadIdx.x == 0) {
        float s = 0.0f;
        #pragma unroll 8
        for (int k = 0; k < NB; ++k) s += sp[k];
        s_val = s;
    }
    __syncthreads();
    const float s = s_val;

    // ---- Write this block's slice of the output ----
    const int per = (total + (int)gridDim.x - 1) / (int)gridDim.x;
    const int j0  = blockIdx.x * per;
    const int j1  = min(j0 + per, total);
    for (int j = j0 + threadIdx.x; j < j1; j += NT) {
        float o = 0.0f;
        if (j < OUTN) o = (__ldg(&out_mask[j]) != 0) ? s : 0.0f;
        out[j] = o;
    }
}

extern "C" void kernel_launch(void* const* d_in, const int* in_sizes, int n_in,
                              void* d_out, int out_size)
{
    const float* x        = (const float*)d_in[0];
    const float* weights  = (const float*)d_in[1];
    const float* min_vals = (const float*)d_in[2];
    const float* max_vals = (const float*)d_in[3];
    const int*   start_p  = (const int*)d_in[4];
    const int*   offsets  = (const int*)d_in[5];
    const int*   sizes    = (const int*)d_in[6];
    const int*   out_mask = (const int*)d_in[7];
    float* out = (float*)d_out;

    int G  = in_sizes[2];
    int Wn = in_sizes[1];
    int D  = Wn / G;
    int B  = in_sizes[0] / D;
    int OUTN = in_sizes[7];

    size_t shmem = (size_t)G * sizeof(float);
    ril_fused_kernel<<<NB, NT, shmem>>>(
        x, weights, min_vals, max_vals, start_p, offsets, sizes,
        out_mask, out, B, D, G, Wn, OUTN, out_size);
}

// round 4
// speedup vs baseline: 1.2284x; 1.2284x over previous
#include <cuda_runtime.h>

#define NT 256
#define NWARP 8
#define CHUNKS 32              // float4 chunks per block
#define COLS_PER_BLOCK 128     // scalar columns per block
#define MAX_PBLOCKS 4096

__device__ float g_partials[MAX_PBLOCKS];

// Kernel 1: block handles 128 columns. Warps parallelize the batch dimension
// (warp w loads rows w, w+8, ...), cross-row sum goes through shared, then
// 128 threads each finish one column (searchsorted + weight gather + v*w).
__global__ void __launch_bounds__(NT)
ril_reduce_kernel(const float* __restrict__ x,
                  const float* __restrict__ weights,
                  const float* __restrict__ min_vals,
                  const float* __restrict__ max_vals,
                  const int* __restrict__ start_pos,
                  const int* __restrict__ offsets,
                  const int* __restrict__ sizes,
                  int B, int D, int G, int Wn)
{
    extern __shared__ float4 sraw[];
    float4 (*sx)[CHUNKS] = (float4 (*)[CHUNKS])sraw;   // [NWARP][CHUNKS] = 4KB
    float* smv = (float*)(sraw + NWARP * CHUNKS);      // G floats

    const int lane = threadIdx.x & 31;
    const int w    = threadIdx.x >> 5;

    // Preload min_vals to shared
    for (int i = threadIdx.x; i < G; i += NT) smv[i] = __ldg(&min_vals[i]);

    // Row-load phase: warp w accumulates rows w, w+NWARP, ... for its chunk
    const int chunk = blockIdx.x * CHUNKS + lane;       // float4 index
    float4 a4 = make_float4(0.f, 0.f, 0.f, 0.f);
    if (chunk * 4 + 3 < D) {
        for (int b = w; b < B; b += NWARP) {
            const float4 xv = __ldg((const float4*)(x + (size_t)b * D) + chunk);
            a4.x += xv.x; a4.y += xv.y; a4.z += xv.z; a4.w += xv.w;
        }
    } else if (chunk * 4 < D) {
        // partial chunk: load scalars
        float tmp[4] = {0.f, 0.f, 0.f, 0.f};
        for (int b = w; b < B; b += NWARP)
            for (int k = 0; k < 4; ++k)
                if (chunk * 4 + k < D) tmp[k] += x[(size_t)b * D + chunk * 4 + k];
        a4.x = tmp[0]; a4.y = tmp[1]; a4.z = tmp[2]; a4.w = tmp[3];
    }
    sx[w][lane] = a4;
    __syncthreads();

    // Compute phase: threads 0..127, one scalar column each
    float acc = 0.0f;
    const int col = blockIdx.x * COLS_PER_BLOCK + threadIdx.x;
    if (threadIdx.x < COLS_PER_BLOCK && col < D) {
        const int c_chunk = threadIdx.x >> 2;
        const int c_comp  = threadIdx.x & 3;
        float s = 0.0f;
        #pragma unroll
        for (int ww = 0; ww < NWARP; ++ww) {
            const float* p = (const float*)&sx[ww][c_chunk];
            s += p[c_comp];
        }
        const float vv = s / (float)B;

        // searchsorted(min_vals, v, 'right') - 1
        int lo = 0, hi = G;
        while (lo < hi) {
            int mid = (lo + hi) >> 1;
            if (smv[mid] <= vv) lo = mid + 1; else hi = mid;
        }
        int g  = lo - 1;
        int gc = min(max(g, 0), G - 1);
        bool in_range = (g >= 0) && (vv >= smv[gc]) && (vv <= __ldg(&max_vals[gc]));
        int pos = col - __ldg(&start_pos[gc]);
        bool valid = in_range && (pos >= 0) && (pos < __ldg(&sizes[gc]));
        int widx = __ldg(&offsets[gc]) + pos;
        widx = min(max(widx, 0), Wn - 1);
        float wv = valid ? __ldg(&weights[widx]) : 0.0f;
        acc = vv * wv;
    }

    // Block reduce 256 lanes (upper 128 are zero)
    #pragma unroll
    for (int o = 16; o > 0; o >>= 1)
        acc += __shfl_down_sync(0xffffffffu, acc, o);
    __shared__ float red[NWARP];
    if (lane == 0) red[w] = acc;
    __syncthreads();
    if (threadIdx.x == 0) {
        float p = 0.0f;
        #pragma unroll
        for (int k = 0; k < NWARP; ++k) p += red[k];
        g_partials[blockIdx.x] = p;
    }
}

// Kernel 2: each block reduces the (L2-resident) partials deterministically,
// then writes its 1024-element slice of the output. out_mask is int32.
__global__ void __launch_bounds__(1024)
ril_finalize_kernel(const int* __restrict__ out_mask,
                    float* __restrict__ out,
                    int nPartials, int OUTN, int total)
{
    float acc = 0.0f;
    // fixed assignment: thread k sums partials k, k+1024, ... (deterministic)
    for (int i = threadIdx.x; i < nPartials; i += 1024)
        acc += g_partials[i];
    #pragma unroll
    for (int o = 16; o > 0; o >>= 1)
        acc += __shfl_down_sync(0xffffffffu, acc, o);
    __shared__ float red[32];
    __shared__ float s_val;
    const int lane = threadIdx.x & 31;
    const int wid  = threadIdx.x >> 5;
    if (lane == 0) red[wid] = acc;
    __syncthreads();
    if (threadIdx.x == 0) {
        float s = 0.0f;
        #pragma unroll
        for (int k = 0; k < 32; ++k) s += red[k];
        s_val = s;
    }
    __syncthreads();
    const float s = s_val;

    const int j = blockIdx.x * 1024 + threadIdx.x;
    if (j < total) {
        float o = 0.0f;
        if (j < OUTN) o = (__ldg(&out_mask[j]) != 0) ? s : 0.0f;
        out[j] = o;
    }
}

extern "C" void kernel_launch(void* const* d_in, const int* in_sizes, int n_in,
                              void* d_out, int out_size)
{
    const float* x        = (const float*)d_in[0];
    const float* weights  = (const float*)d_in[1];
    const float* min_vals = (const float*)d_in[2];
    const float* max_vals = (const float*)d_in[3];
    const int*   start_p  = (const int*)d_in[4];
    const int*   offsets  = (const int*)d_in[5];
    const int*   sizes    = (const int*)d_in[6];
    const int*   out_mask = (const int*)d_in[7];
    float* out = (float*)d_out;

    int G  = in_sizes[2];
    int Wn = in_sizes[1];
    int D  = Wn / G;
    int B  = in_sizes[0] / D;
    int OUTN = in_sizes[7];

    int blocks = (D + COLS_PER_BLOCK - 1) / COLS_PER_BLOCK;   // 512 for D=65536
    if (blocks > MAX_PBLOCKS) blocks = MAX_PBLOCKS;           // not hit here
    size_t shmem = NWARP * CHUNKS * sizeof(float4) + (size_t)G * sizeof(float);

    ril_reduce_kernel<<<blocks, NT, shmem>>>(
        x, weights, min_vals, max_vals, start_p, offsets, sizes, B, D, G, Wn);

    int fblocks = (out_size + 1023) / 1024;
    ril_finalize_kernel<<<fblocks, 1024>>>(out_mask, out, blocks, OUTN, out_size);
}